// round 10
// baseline (speedup 1.0000x reference)
#include <cuda_runtime.h>
#include <cuda_fp16.h>
#include <cstdint>

#define NB 8
#define LQ 256
#define LK 256
#define HH 256
#define DV 256
#define MASK_VALUE -1000000.0f

// Scratch (allocation-free rule: device globals)
__device__ float g_Qp[NB * LQ * HH];
__device__ float g_Kp[NB * LK * HH];
__device__ float g_S[NB * LQ * LK];

__device__ __forceinline__ uint32_t f2tf(float x) {
    uint32_t r;
    asm("cvt.rna.tf32.f32 %0, %1;" : "=r"(r) : "f"(x));
    return r;
}

__device__ __forceinline__ uint4 tf4(float4 v) {
    return make_uint4(f2tf(v.x), f2tf(v.y), f2tf(v.z), f2tf(v.w));
}

__device__ __forceinline__ __half2 tanh2(__half2 x) {
    uint32_t xi = *(uint32_t*)&x;
    uint32_t yi;
    asm("tanh.approx.f16x2 %0, %1;" : "=r"(yi) : "r"(xi));
    return *(__half2*)&yi;
}

// D += A(16x8,row) * B(8x8,col)  in tf32, fp32 accum
__device__ __forceinline__ void mma8(float* d, const uint32_t* a, const uint32_t* b) {
    asm("mma.sync.aligned.m16n8k8.row.col.f32.tf32.tf32.f32 "
        "{%0,%1,%2,%3}, {%4,%5,%6,%7}, {%8,%9}, {%0,%1,%2,%3};"
        : "+f"(d[0]), "+f"(d[1]), "+f"(d[2]), "+f"(d[3])
        : "r"(a[0]), "r"(a[1]), "r"(a[2]), "r"(a[3]), "r"(b[0]), "r"(b[1]));
}

#define TS 36  // smem stride, k-contiguous tiles (fragment LDS conflict-free)
#define VS 35  // smem stride, transposed V tile (<=2-way)

// ---------------------------------------------------------------------------
// Projection NT GEMM (tf32, single-warp blocks): C[m][n] = sum_k X[m][k]*W[n][k]
// One warp per block, 32m x 32n tile, kc=32 double-buffered, warp tile = CTA
// tile -> 16 LDS per 8 mma, no __syncthreads. grid (8, 64, 2) = 1024 blocks.
// ---------------------------------------------------------------------------
__global__ void __launch_bounds__(32) proj_kernel(
    const float* __restrict__ Xq, const float* __restrict__ Wq,
    const float* __restrict__ Xk, const float* __restrict__ Wk) {
    const float* X;
    const float* W;
    float* C;
    if (blockIdx.z == 0) { X = Xq; W = Wq; C = g_Qp; }
    else                 { X = Xk; W = Wk; C = g_Kp; }

    __shared__ uint32_t Xs[2][32 * TS];
    __shared__ uint32_t Ws[2][32 * TS];

    const int lane = threadIdx.x;
    const int gid = lane >> 2;   // 0..7
    const int tig = lane & 3;    // 0..3
    const int sr = lane >> 3;    // staging row subgroup 0..3
    const int sj = lane & 7;     // staging float4 index 0..7
    const int m0 = blockIdx.y * 32;
    const int n0 = blockIdx.x * 32;

    float d[2][4][4];
    #pragma unroll
    for (int i = 0; i < 2; i++)
        #pragma unroll
        for (int j = 0; j < 4; j++)
            #pragma unroll
            for (int e = 0; e < 4; e++) d[i][j][e] = 0.f;

    for (int c = 0; c < 8; c++) {
        uint32_t* XB = Xs[c & 1];
        uint32_t* WB = Ws[c & 1];
        const int kb = c * 32;
        #pragma unroll
        for (int it = 0; it < 8; it++) {
            const int r = it * 4 + sr;
            float4 xv = *(const float4*)&X[(m0 + r) * 256 + kb + sj * 4];
            float4 wv = *(const float4*)&W[(n0 + r) * 256 + kb + sj * 4];
            *(uint4*)&XB[r * TS + sj * 4] = tf4(xv);
            *(uint4*)&WB[r * TS + sj * 4] = tf4(wv);
        }
        __syncwarp();

        #pragma unroll
        for (int ks = 0; ks < 4; ks++) {
            const int kk = ks * 8;
            uint32_t a[2][4], b[4][2];
            #pragma unroll
            for (int i = 0; i < 2; i++) {
                const int r = i * 16 + gid;
                a[i][0] = XB[r * TS + kk + tig];
                a[i][1] = XB[(r + 8) * TS + kk + tig];
                a[i][2] = XB[r * TS + kk + tig + 4];
                a[i][3] = XB[(r + 8) * TS + kk + tig + 4];
            }
            #pragma unroll
            for (int jn = 0; jn < 4; jn++) {
                const int n = jn * 8 + gid;
                b[jn][0] = WB[n * TS + kk + tig];
                b[jn][1] = WB[n * TS + kk + tig + 4];
            }
            #pragma unroll
            for (int i = 0; i < 2; i++)
                #pragma unroll
                for (int jn = 0; jn < 4; jn++) mma8(d[i][jn], a[i], b[jn]);
        }
        __syncwarp();
    }

    #pragma unroll
    for (int i = 0; i < 2; i++)
        #pragma unroll
        for (int jn = 0; jn < 4; jn++) {
            const int row = m0 + i * 16 + gid;
            const int col = n0 + jn * 8 + tig * 2;
            *(float2*)&C[row * 256 + col] = make_float2(d[i][jn][0], d[i][jn][1]);
            *(float2*)&C[(row + 8) * 256 + col] = make_float2(d[i][jn][2], d[i][jn][3]);
        }
}

// ---------------------------------------------------------------------------
// Scores (fp16x2 tanh): S[b][q][k] = sum_h Wv[h]*tanh(Qp[b][q][h]+Kp[b][k][h])
// K packed in half2 pairs, Q duplicated in half2: one MUFU.TANH.f16x2 does
// two tanh. Accumulation stays fp32. Masked 32x32 tiles skip all compute.
// ---------------------------------------------------------------------------
__global__ void scores_kernel(const float* __restrict__ Wv,
                              const int* __restrict__ vlens) {
    const int b = blockIdx.z;
    const int q0 = blockIdx.y * 32;
    const int k0 = blockIdx.x * 32;
    const int tid = threadIdx.x;
    const int tx = tid & 15;    // k-pair index: k = k0 + 2*tx + {0,1}
    const int ty = tid >> 4;    // q: q0 + 2*ty + {0,1}
    const int vl = vlens[b];
    float* S = g_S + b * LQ * LK;

    if (k0 >= vl) {
        const float2 mv = make_float2(MASK_VALUE, MASK_VALUE);
        #pragma unroll
        for (int i = 0; i < 2; i++)
            *(float2*)&S[(q0 + 2 * ty + i) * LK + k0 + 2 * tx] = mv;
        return;
    }

    __shared__ __half2 Qs[64][34];  // dup(q) per (h, q)
    __shared__ __half2 Ks[64][18];  // (k0,k1) pair per (h, kpair)
    __shared__ float sWv[256];

    sWv[tid] = Wv[tid];

    const float* Qb = g_Qp + (b * LQ + q0) * HH;
    const float* Kb = g_Kp + (b * LK + k0) * HH;

    float a00 = 0.f, a01 = 0.f, a10 = 0.f, a11 = 0.f;

    for (int h0 = 0; h0 < HH; h0 += 64) {
        #pragma unroll
        for (int j = 0; j < 8; j++) {
            int idx = tid + j * 256;
            int h = idx & 63;
            int qi = idx >> 6;
            float q = Qb[qi * HH + h0 + h];
            Qs[h][qi] = __float2half2_rn(q);
        }
        #pragma unroll
        for (int j = 0; j < 4; j++) {
            int idx = tid + j * 256;
            int h = idx & 63;
            int kj = idx >> 6;
            float ka = Kb[(2 * kj) * HH + h0 + h];
            float kb2 = Kb[(2 * kj + 1) * HH + h0 + h];
            Ks[h][kj] = __floats2half2_rn(ka, kb2);
        }
        __syncthreads();
        #pragma unroll 8
        for (int h = 0; h < 64; h++) {
            __half2 kp = Ks[h][tx];
            __half2 s0 = __hadd2(Qs[h][2 * ty], kp);
            __half2 s1 = __hadd2(Qs[h][2 * ty + 1], kp);
            float2 f0 = __half22float2(tanh2(s0));
            float2 f1 = __half22float2(tanh2(s1));
            float wv = sWv[h0 + h];
            a00 += wv * f0.x;
            a01 += wv * f0.y;
            a10 += wv * f1.x;
            a11 += wv * f1.y;
        }
        __syncthreads();
    }

    const int kA = k0 + 2 * tx;
    const int kB = kA + 1;
    const int qA = q0 + 2 * ty;
    const int qB = qA + 1;
    S[qA * LK + kA] = (kA < vl) ? a00 : MASK_VALUE;
    S[qA * LK + kB] = (kB < vl) ? a01 : MASK_VALUE;
    S[qB * LK + kA] = (kA < vl) ? a10 : MASK_VALUE;
    S[qB * LK + kB] = (kB < vl) ? a11 : MASK_VALUE;
}

// ---------------------------------------------------------------------------
// Softmax over axis=1 (QUERY axis) per (b, k) column — reference quirk.
// ---------------------------------------------------------------------------
__global__ void softmax_kernel() {
    const int b = blockIdx.y;
    const int tx = threadIdx.x & 31;
    const int ty = threadIdx.x >> 5;  // 0..7
    const int k = blockIdx.x * 32 + tx;
    float* S = g_S + b * LQ * LK;

    float vals[32];
    float m = -3.4e38f;
    #pragma unroll
    for (int i = 0; i < 32; i++) {
        vals[i] = S[(i * 8 + ty) * LK + k];
        m = fmaxf(m, vals[i]);
    }

    __shared__ float red[8][33];
    red[ty][tx] = m;
    __syncthreads();
    float M = red[0][tx];
    #pragma unroll
    for (int t = 1; t < 8; t++) M = fmaxf(M, red[t][tx]);
    __syncthreads();

    float s = 0.f;
    #pragma unroll
    for (int i = 0; i < 32; i++) {
        vals[i] = __expf(vals[i] - M);
        s += vals[i];
    }
    red[ty][tx] = s;
    __syncthreads();
    float SUM = 0.f;
    #pragma unroll
    for (int t = 0; t < 8; t++) SUM += red[t][tx];

    const float inv = 1.0f / SUM;
    #pragma unroll
    for (int i = 0; i < 32; i++)
        S[(i * 8 + ty) * LK + k] = vals[i] * inv;
}

// ---------------------------------------------------------------------------
// Output NN GEMM (tf32, single-warp blocks): out[b][q][d]=sum_k A[b][q][k]*V[b][k][d]
// One warp per block, 32q x 32d tile; V staged transposed [d][k] (stride 35).
// grid (8, 8, 8) = 512 blocks.
// ---------------------------------------------------------------------------
__global__ void __launch_bounds__(32) out_kernel(
    const float* __restrict__ Vv, float* __restrict__ out) {
    const int b = blockIdx.z;
    const int q0 = blockIdx.y * 32;
    const int d0 = blockIdx.x * 32;
    const int lane = threadIdx.x;
    const int gid = lane >> 2;
    const int tig = lane & 3;
    const int sr = lane >> 3;
    const int sj = lane & 7;

    const float* A = g_S + b * LQ * LK;
    const float* V = Vv + b * LK * DV;

    __shared__ uint32_t As[2][32 * TS];
    __shared__ uint32_t Vs[2][32 * VS];

    float d[2][4][4];
    #pragma unroll
    for (int i = 0; i < 2; i++)
        #pragma unroll
        for (int j = 0; j < 4; j++)
            #pragma unroll
            for (int e = 0; e < 4; e++) d[i][j][e] = 0.f;

    for (int c = 0; c < 8; c++) {
        uint32_t* AB = As[c & 1];
        uint32_t* VB = Vs[c & 1];
        const int kb = c * 32;
        #pragma unroll
        for (int it = 0; it < 8; it++) {
            const int r = it * 4 + sr;
            float4 av = *(const float4*)&A[(q0 + r) * LK + kb + sj * 4];
            float4 vv = *(const float4*)&V[(kb + r) * DV + d0 + sj * 4];
            *(uint4*)&AB[r * TS + sj * 4] = tf4(av);
            const int dc = sj * 4;
            VB[(dc + 0) * VS + r] = f2tf(vv.x);
            VB[(dc + 1) * VS + r] = f2tf(vv.y);
            VB[(dc + 2) * VS + r] = f2tf(vv.z);
            VB[(dc + 3) * VS + r] = f2tf(vv.w);
        }
        __syncwarp();

        #pragma unroll
        for (int ks = 0; ks < 4; ks++) {
            const int kk = ks * 8;
            uint32_t a[2][4], bfr[4][2];
            #pragma unroll
            for (int i = 0; i < 2; i++) {
                const int r = i * 16 + gid;
                a[i][0] = AB[r * TS + kk + tig];
                a[i][1] = AB[(r + 8) * TS + kk + tig];
                a[i][2] = AB[r * TS + kk + tig + 4];
                a[i][3] = AB[(r + 8) * TS + kk + tig + 4];
            }
            #pragma unroll
            for (int jn = 0; jn < 4; jn++) {
                const int n = jn * 8 + gid;
                bfr[jn][0] = VB[n * VS + kk + tig];
                bfr[jn][1] = VB[n * VS + kk + tig + 4];
            }
            #pragma unroll
            for (int i = 0; i < 2; i++)
                #pragma unroll
                for (int jn = 0; jn < 4; jn++) mma8(d[i][jn], a[i], bfr[jn]);
        }
        __syncwarp();
    }

    float* O = out + b * LQ * DV;
    #pragma unroll
    for (int i = 0; i < 2; i++)
        #pragma unroll
        for (int jn = 0; jn < 4; jn++) {
            const int row = q0 + i * 16 + gid;
            const int col = d0 + jn * 8 + tig * 2;
            *(float2*)&O[row * DV + col] = make_float2(d[i][jn][0], d[i][jn][1]);
            *(float2*)&O[(row + 8) * DV + col] = make_float2(d[i][jn][2], d[i][jn][3]);
        }
}

extern "C" void kernel_launch(void* const* d_in, const int* in_sizes, int n_in,
                              void* d_out, int out_size) {
    const float* queries    = (const float*)d_in[0];
    const float* keyes      = (const float*)d_in[1];
    const float* values     = (const float*)d_in[2];
    const int*   valid_lens = (const int*)d_in[3];
    const float* W_q        = (const float*)d_in[4];
    const float* W_k        = (const float*)d_in[5];
    const float* W_v        = (const float*)d_in[6];
    float* out = (float*)d_out;

    proj_kernel<<<dim3(8, 64, 2), 32>>>(queries, W_q, keyes, W_k);
    scores_kernel<<<dim3(8, 8, 8), 256>>>(W_v, valid_lens);
    softmax_kernel<<<dim3(8, 8), 256>>>();
    out_kernel<<<dim3(8, 8, 8), 32>>>(values, out);
}